// round 14
// baseline (speedup 1.0000x reference)
#include <cuda_runtime.h>
#include <cuda_fp16.h>
#include <cstdint>
#include <math.h>

// Problem constants
#define B_  32
#define T_  256
#define H_  1024
#define G4  4096
#define K_  1024
#define M_  (B_*T_)       // 8192
#define NCTA 128

// ---------------- device scratch ----------------
__device__ __half g_xh [M_*K_];       // fp16 x
__device__ __half g_Wh [2*G4*K_];     // fp16 Wih0, Wih1
__device__ float  g_ih [M_*G4];       // input projection (fp32)
__device__ __half g_y1h[M_*H_];       // layer-0 output (fp16)
__device__ __half g_hA [B_*H_];
__device__ __half g_hB [B_*H_];
__device__ unsigned g_bar;
__device__ unsigned g_flag;

// ---------------- ptx helpers ----------------
__device__ __forceinline__ void mma_f16(float* c, const uint32_t* a, const uint32_t* b) {
    asm volatile(
        "mma.sync.aligned.m16n8k16.row.col.f32.f16.f16.f32 "
        "{%0,%1,%2,%3}, {%4,%5,%6,%7}, {%8,%9}, {%0,%1,%2,%3};\n"
        : "+f"(c[0]), "+f"(c[1]), "+f"(c[2]), "+f"(c[3])
        : "r"(a[0]), "r"(a[1]), "r"(a[2]), "r"(a[3]), "r"(b[0]), "r"(b[1]));
}

__device__ __forceinline__ void ldsm_x4(uint32_t& r0, uint32_t& r1, uint32_t& r2, uint32_t& r3,
                                        uint32_t addr) {
    asm volatile("ldmatrix.sync.aligned.m8n8.x4.shared.b16 {%0,%1,%2,%3}, [%4];"
                 : "=r"(r0), "=r"(r1), "=r"(r2), "=r"(r3) : "r"(addr));
}

#define CP_ASYNC_CG(dst, src) \
    asm volatile("cp.async.cg.shared.global [%0], [%1], 16;\n" :: "r"(dst), "l"(src))
#define CP_COMMIT() asm volatile("cp.async.commit_group;\n" ::: "memory")
#define CP_WAIT(N)  asm volatile("cp.async.wait_group %0;\n" :: "n"(N) : "memory")

__device__ __forceinline__ float sig_f(float x) {
    return __fdividef(1.f, 1.f + __expf(-x));
}
__device__ __forceinline__ float tanh_f(float x) {
    float e = __expf(2.f * x);
    return 1.f - __fdividef(2.f, e + 1.f);
}

// ---------------- fp32 -> fp16 conversion ----------------
__global__ void round_half_kernel(const float* __restrict__ src, int n, int dsel) {
    __half* dst = (dsel == 0) ? g_xh : (g_Wh + (size_t)(dsel - 1) * (G4 * K_));
    int i4 = (blockIdx.x * blockDim.x + threadIdx.x) * 4;
    if (i4 < n) {
        float4 v = *(const float4*)(src + i4);
        *(__half2*)(dst + i4)     = __floats2half2_rn(v.x, v.y);
        *(__half2*)(dst + i4 + 2) = __floats2half2_rn(v.z, v.w);
    }
}

// ---------------- input projection GEMM: 3-stage pipeline (R11 winner) ----------------
#define BM 128
#define BN 128
#define BKH 32
#define GSTR 40
#define ASZ (BM * GSTR * 2)              // bytes per stage (10240)
#define GSMEM (3 * 2 * ASZ)              // 61440 bytes

__global__ __launch_bounds__(256, 2)
void gemm_ih_kernel(int asel, int woff, const float* __restrict__ bias) {
    const __half* A = asel ? g_y1h : g_xh;
    const __half* W = g_Wh + (size_t)woff * (G4 * K_);

    extern __shared__ __half gsm[];
    uint32_t sa = (uint32_t)__cvta_generic_to_shared(gsm);            // 3 A stages
    uint32_t sb = sa + 3 * ASZ;                                        // 3 B stages

    int tid  = threadIdx.x;
    int bm   = blockIdx.y * BM;
    int bn   = blockIdx.x * BN;
    int warp = tid >> 5, lane = tid & 31;
    int gid  = lane >> 2, tig = lane & 3;
    int wm   = (warp & 3) * 32;
    int wn   = (warp >> 2) * 64;

    int r0   = tid >> 2;
    int gcol = (tid & 3) * 8;
    const __half* Ap = A + (size_t)(bm + r0) * K_ + gcol;
    const __half* Wp = W + (size_t)(bn + r0) * K_ + gcol;
    uint32_t da0 = sa + (uint32_t)(r0 * GSTR + gcol) * 2;
    uint32_t da1 = sa + (uint32_t)((r0 + 64) * GSTR + gcol) * 2;
    uint32_t db0 = sb + (uint32_t)(r0 * GSTR + gcol) * 2;
    uint32_t db1 = sb + (uint32_t)((r0 + 64) * GSTR + gcol) * 2;

    uint32_t a_off = (uint32_t)(((lane & 7) + ((lane >> 3) & 1) * 8) * GSTR + (lane >> 4) * 8) * 2;
    uint32_t b_off = (uint32_t)(((lane & 7) + ((lane >> 4) & 1) * 8) * GSTR + ((lane >> 3) & 1) * 8) * 2;

    float c[2][8][4];
#pragma unroll
    for (int i = 0; i < 2; i++)
#pragma unroll
        for (int j = 0; j < 8; j++)
#pragma unroll
            for (int q = 0; q < 4; q++) c[i][j][q] = 0.f;

#define G_LOAD(it, stg_)                                                      \
    do {                                                                      \
        int k_ = (it) * BKH;                                                  \
        uint32_t so_ = (uint32_t)(stg_) * ASZ;                                \
        CP_ASYNC_CG(da0 + so_, Ap + k_);                                      \
        CP_ASYNC_CG(da1 + so_, Ap + (size_t)64 * K_ + k_);                    \
        CP_ASYNC_CG(db0 + so_, Wp + k_);                                      \
        CP_ASYNC_CG(db1 + so_, Wp + (size_t)64 * K_ + k_);                    \
        CP_COMMIT();                                                          \
    } while (0)

    const int NIT = K_ / BKH;   // 32
    G_LOAD(0, 0);               // group g0 -> stage 0
    G_LOAD(1, 1);               // group g1 -> stage 1

    int stg = 0;
    for (int it = 0; it < NIT; it++) {
        // pending before wait: {g_it, g_{it+1}} (2) except last iter: {g_it} (1)
        if (it == NIT - 1) CP_WAIT(0);
        else               CP_WAIT(1);
        __syncthreads();   // g_it visible AND all reads of stage (stg+2)%3 done

        if (it + 2 < NIT) {
            int nst = stg + 2; if (nst >= 3) nst -= 3;
            G_LOAD(it + 2, nst);
        }

        uint32_t sAs = sa + (uint32_t)stg * ASZ;
        uint32_t sBs = sb + (uint32_t)stg * ASZ;
#pragma unroll
        for (int ks = 0; ks < 2; ks++) {
            uint32_t af[2][4], bf[8][2];
#pragma unroll
            for (int mi = 0; mi < 2; mi++)
                ldsm_x4(af[mi][0], af[mi][1], af[mi][2], af[mi][3],
                        sAs + (uint32_t)((wm + mi * 16) * GSTR) * 2 + a_off + ks * 32);
#pragma unroll
            for (int nj = 0; nj < 4; nj++)
                ldsm_x4(bf[2 * nj][0], bf[2 * nj][1], bf[2 * nj + 1][0], bf[2 * nj + 1][1],
                        sBs + (uint32_t)((wn + nj * 16) * GSTR) * 2 + b_off + ks * 32);
#pragma unroll
            for (int mi = 0; mi < 2; mi++)
#pragma unroll
                for (int nj = 0; nj < 8; nj++)
                    mma_f16(c[mi][nj], af[mi], bf[nj]);
        }
        if (++stg >= 3) stg = 0;
    }
#undef G_LOAD

#pragma unroll
    for (int mi = 0; mi < 2; mi++) {
#pragma unroll
        for (int nj = 0; nj < 8; nj++) {
            int m0 = bm + wm + mi * 16 + gid;
            int n0 = bn + wn + nj * 8 + 2 * tig;
            float b0v = bias[n0], b1v = bias[n0 + 1];
            size_t o = (size_t)m0 * G4 + n0;
            g_ih[o]                      = c[mi][nj][0] + b0v;
            g_ih[o + 1]                  = c[mi][nj][1] + b1v;
            g_ih[o + (size_t)8 * G4]     = c[mi][nj][2] + b0v;
            g_ih[o + (size_t)8 * G4 + 1] = c[mi][nj][3] + b1v;
        }
    }
}

// ---------------- zero h / barrier ----------------
__global__ void zero_state_kernel() {
    int i = blockIdx.x * blockDim.x + threadIdx.x;
    if (i < B_ * H_) {
        g_hA[i] = __float2half(0.f);
        g_hB[i] = __float2half(0.f);
    }
    if (i == 0) { g_bar = 0u; g_flag = 0u; }
}

// ---------------- persistent recurrence kernel ----------------
// R13 structure; grid barrier changed to sense-flag form: arrivals on g_bar
// (red.release), only CTA0/tid0 polls the counter and publishes g_flag;
// everyone else polls the read-only flag line (no atomic contention).
#define WSTR 1032
#define HSTR 1032
#define PERSIST_SMEM ((32*WSTR + 32*HSTR) * 2 + 2 * 32 * 33 * 4)

__global__ __launch_bounds__(256, 1)
void lstm_persist_kernel(const float* __restrict__ Whh_raw, int outsel,
                         float* __restrict__ out_ext)
{
    extern __shared__ __half smh[];
    __half* Wsm = smh;
    __half* Hsm = Wsm + 32 * WSTR;
    float*  Ps  = (float*)(Hsm + 32 * HSTR);

    int tid  = threadIdx.x;
    int warp = tid >> 5, lane = tid & 31;
    int gid  = lane >> 2, tig = lane & 3;
    int kh   = warp & 1;
    int nj   = (warp >> 1) & 1;
    int mi   = warp >> 2;
    int j0   = blockIdx.x * 8;

#pragma unroll 4
    for (int i = 0; i < 32; i++) {
        int idx = i * 256 + tid;
        int r   = idx >> 8;
        int c4  = idx & 255;
        int g   = r >> 3, jr = r & 7;
        const float4 v = *(const float4*)(Whh_raw + ((size_t)(g * H_ + j0 + jr)) * K_ + c4 * 4);
        *(__half2*)&Wsm[r * WSTR + c4 * 4]     = __floats2half2_rn(v.x, v.y);
        *(__half2*)&Wsm[r * WSTR + c4 * 4 + 2] = __floats2half2_rn(v.z, v.w);
    }

    uint32_t hs_base = (uint32_t)__cvta_generic_to_shared(Hsm);
    uint32_t ws_base = (uint32_t)__cvta_generic_to_shared(Wsm);
    uint32_t a_base = hs_base +
        (uint32_t)((mi * 16 + (lane & 7) + ((lane >> 3) & 1) * 8) * HSTR +
                   (lane >> 4) * 8 + kh * 512) * 2;
    uint32_t b_base = ws_base +
        (uint32_t)((nj * 16 + (lane & 7) + ((lane >> 4) & 1) * 8) * WSTR +
                   ((lane >> 3) & 1) * 8 + kh * 512) * 2;

    int hrow = tid >> 5;
    int hcol = lane * 8;
    int b    = tid >> 3;
    int jj   = tid & 7;
    float c_state = 0.f;
    float* Pk = Ps + kh * (32 * 33);
    bool is_cta0_t0 = (blockIdx.x == 0) && (tid == 0);

    __syncthreads();

    size_t ihbase = ((size_t)b * T_) * G4 + j0 + jj;
    float ih0 = __ldcs(&g_ih[ihbase]);
    float ih1 = __ldcs(&g_ih[ihbase + H_]);
    float ih2 = __ldcs(&g_ih[ihbase + 2 * H_]);
    float ih3 = __ldcs(&g_ih[ihbase + 3 * H_]);

    for (int t = 0; t < T_; t++) {
        const __half* hin  = (t & 1) ? g_hB : g_hA;
        __half*       hout = (t & 1) ? g_hA : g_hB;

        uint4 rv[16];
#pragma unroll
        for (int p = 0; p < 4; p++)
#pragma unroll
            for (int q = 0; q < 4; q++)
                rv[p * 4 + q] = __ldcg((const uint4*)(hin + (size_t)(hrow + 8 * p) * H_ +
                                                       q * 256 + hcol));
#pragma unroll
        for (int p = 0; p < 4; p++)
#pragma unroll
            for (int q = 0; q < 4; q++)
                *(uint4*)&Hsm[(hrow + 8 * p) * HSTR + q * 256 + hcol] = rv[p * 4 + q];
        __syncthreads();

        float acc0[4] = {0.f, 0.f, 0.f, 0.f};
        float acc1[4] = {0.f, 0.f, 0.f, 0.f};
        uint32_t aaddr = a_base, baddr = b_base;
#pragma unroll
        for (int ks = 0; ks < 32; ks++) {
            uint32_t af[4], bl[2], bhh[2];
            ldsm_x4(af[0], af[1], af[2], af[3], aaddr);
            ldsm_x4(bl[0], bl[1], bhh[0], bhh[1], baddr);
            mma_f16(acc0, af, bl);
            mma_f16(acc1, af, bhh);
            aaddr += 32;
            baddr += 32;
        }

        {
            int m = mi * 16 + gid;
            int n = nj * 16 + 2 * tig;
            Pk[m * 33 + n]               = acc0[0];
            Pk[m * 33 + n + 1]           = acc0[1];
            Pk[(m + 8) * 33 + n]         = acc0[2];
            Pk[(m + 8) * 33 + n + 1]     = acc0[3];
            Pk[m * 33 + n + 8]           = acc1[0];
            Pk[m * 33 + n + 9]           = acc1[1];
            Pk[(m + 8) * 33 + n + 8]     = acc1[2];
            Pk[(m + 8) * 33 + n + 9]     = acc1[3];
        }
        __syncthreads();

        float hv;
        __half hr;
        {
            const float* P0 = Ps;
            const float* P1 = Ps + 32 * 33;
            float ipre = P0[b * 33 + jj]      + P1[b * 33 + jj]      + ih0;
            float fpre = P0[b * 33 + 8 + jj]  + P1[b * 33 + 8 + jj]  + ih1;
            float gpre = P0[b * 33 + 16 + jj] + P1[b * 33 + 16 + jj] + ih2;
            float opre = P0[b * 33 + 24 + jj] + P1[b * 33 + 24 + jj] + ih3;
            float iv = sig_f(ipre);
            float fv = sig_f(fpre);
            float gv = tanh_f(gpre);
            float ov = sig_f(opre);
            c_state = fv * c_state + iv * gv;
            hv = ov * tanh_f(c_state);
            hr = __float2half_rn(hv);
            unsigned short hb16 = __half_as_ushort(hr);
            asm volatile("st.global.cg.u16 [%0], %1;"
                         :: "l"(hout + b * H_ + j0 + jj), "h"(hb16) : "memory");
        }

        // ---- grid barrier: counter arrivals + single publisher + flag poll ----
        __syncthreads();                 // all hout stores ordered CTA-wide
        if (tid == 0) {
            asm volatile("red.release.gpu.global.add.u32 [%0], %1;"
                         :: "l"(&g_bar), "r"(1u) : "memory");
        }

        // hidden under the wait window: out store + next-step ih prefetch
        {
            size_t oidx = ((size_t)(b * T_ + t)) * H_ + j0 + jj;
            if (outsel) out_ext[oidx] = hv;
            else        g_y1h[oidx]   = hr;
            if (t + 1 < T_) {
                size_t ihn = ((size_t)(b * T_ + t + 1)) * G4 + j0 + jj;
                ih0 = __ldcs(&g_ih[ihn]);
                ih1 = __ldcs(&g_ih[ihn + H_]);
                ih2 = __ldcs(&g_ih[ihn + 2 * H_]);
                ih3 = __ldcs(&g_ih[ihn + 3 * H_]);
            }
        }

        // CTA0/tid0 polls the counter and publishes the step flag
        if (is_cta0_t0) {
            unsigned target = (unsigned)NCTA * (unsigned)(t + 1);
            unsigned v;
            do {
                asm volatile("ld.acquire.gpu.global.u32 %0, [%1];"
                             : "=r"(v) : "l"(&g_bar));
            } while (v < target);
            asm volatile("st.release.gpu.global.u32 [%0], %1;"
                         :: "l"(&g_flag), "r"((unsigned)(t + 1)) : "memory");
        }

        // everyone polls the read-only flag line
        {
            unsigned ft = (unsigned)(t + 1);
            if (lane == 0) {
                unsigned v;
                do {
                    asm volatile("ld.acquire.gpu.global.u32 %0, [%1];"
                                 : "=r"(v) : "l"(&g_flag));
                } while (v < ft);
            }
            __syncwarp();
        }
    }
}

// ---------------- launch ----------------
extern "C" void kernel_launch(void* const* d_in, const int* in_sizes, int n_in,
                              void* d_out, int out_size) {
    const float* x    = (const float*)d_in[0];
    const float* Wih0 = (const float*)d_in[1];
    const float* Whh0 = (const float*)d_in[2];
    const float* b0   = (const float*)d_in[3];
    const float* Wih1 = (const float*)d_in[4];
    const float* Whh1 = (const float*)d_in[5];
    const float* b1   = (const float*)d_in[6];
    float* out = (float*)d_out;

    static int attr_set = 0;
    if (!attr_set) {
        cudaFuncSetAttribute(lstm_persist_kernel,
                             cudaFuncAttributeMaxDynamicSharedMemorySize, PERSIST_SMEM);
        cudaFuncSetAttribute(gemm_ih_kernel,
                             cudaFuncAttributeMaxDynamicSharedMemorySize, GSMEM);
        attr_set = 1;
    }

    const int nx = M_ * K_;
    const int nw = G4 * K_;
    round_half_kernel<<<(nx / 4 + 255) / 256, 256>>>(x,    nx, 0);
    round_half_kernel<<<(nw / 4 + 255) / 256, 256>>>(Wih0, nw, 1);
    round_half_kernel<<<(nw / 4 + 255) / 256, 256>>>(Wih1, nw, 2);

    dim3 ggrid(G4 / BN, M_ / BM);   // (32, 64)

    // layer 0
    gemm_ih_kernel<<<ggrid, 256, GSMEM>>>(0, 0, b0);
    zero_state_kernel<<<(B_ * H_ + 1023) / 1024, 1024>>>();
    lstm_persist_kernel<<<NCTA, 256, PERSIST_SMEM>>>(Whh0, 0, nullptr);

    // layer 1
    gemm_ih_kernel<<<ggrid, 256, GSMEM>>>(1, 1, b1);
    zero_state_kernel<<<(B_ * H_ + 1023) / 1024, 1024>>>();
    lstm_persist_kernel<<<NCTA, 256, PERSIST_SMEM>>>(Whh1, 1, out);
}

// round 15
// speedup vs baseline: 1.1913x; 1.1913x over previous
#include <cuda_runtime.h>
#include <cuda_fp16.h>
#include <cstdint>
#include <math.h>

// Problem constants
#define B_  32
#define T_  256
#define H_  1024
#define G4  4096
#define K_  1024
#define M_  (B_*T_)       // 8192
#define NCTA 128

// ---------------- device scratch ----------------
__device__ __half g_xh [M_*K_];       // fp16 x
__device__ __half g_Wh [2*G4*K_];     // fp16 Wih0, Wih1
__device__ float  g_ih [M_*G4];       // input projection (fp32)
__device__ __half g_y1h[M_*H_];       // layer-0 output (fp16)
__device__ __half g_hA [B_*H_];
__device__ __half g_hB [B_*H_];
__device__ unsigned g_bar;

// ---------------- ptx helpers ----------------
__device__ __forceinline__ void mma_f16(float* c, const uint32_t* a, const uint32_t* b) {
    asm volatile(
        "mma.sync.aligned.m16n8k16.row.col.f32.f16.f16.f32 "
        "{%0,%1,%2,%3}, {%4,%5,%6,%7}, {%8,%9}, {%0,%1,%2,%3};\n"
        : "+f"(c[0]), "+f"(c[1]), "+f"(c[2]), "+f"(c[3])
        : "r"(a[0]), "r"(a[1]), "r"(a[2]), "r"(a[3]), "r"(b[0]), "r"(b[1]));
}

__device__ __forceinline__ void ldsm_x4(uint32_t& r0, uint32_t& r1, uint32_t& r2, uint32_t& r3,
                                        uint32_t addr) {
    asm volatile("ldmatrix.sync.aligned.m8n8.x4.shared.b16 {%0,%1,%2,%3}, [%4];"
                 : "=r"(r0), "=r"(r1), "=r"(r2), "=r"(r3) : "r"(addr));
}

#define CP_ASYNC_CG(dst, src) \
    asm volatile("cp.async.cg.shared.global [%0], [%1], 16;\n" :: "r"(dst), "l"(src))
#define CP_COMMIT() asm volatile("cp.async.commit_group;\n" ::: "memory")
#define CP_WAIT(N)  asm volatile("cp.async.wait_group %0;\n" :: "n"(N) : "memory")

__device__ __forceinline__ float sig_f(float x) {
    return __fdividef(1.f, 1.f + __expf(-x));
}
__device__ __forceinline__ float tanh_f(float x) {
    float e = __expf(2.f * x);
    return 1.f - __fdividef(2.f, e + 1.f);
}

// ---------------- fused prep: fp16 rounds + h zero + counter init ----------------
// quads: [0, nx/4) -> x, [nx/4, nx/4+nw/4) -> Wih0, next nw/4 -> Wih1
#define NXQ (M_*K_/4)        // 2097152
#define NWQ (G4*K_/4)        // 1048576
#define PREPQ (NXQ + 2*NWQ)  // 4194304

__global__ void prep_kernel(const float* __restrict__ x,
                            const float* __restrict__ Wih0,
                            const float* __restrict__ Wih1) {
    int gid = blockIdx.x * blockDim.x + threadIdx.x;
    if (gid < PREPQ) {
        const float* src;
        __half* dst;
        int q;
        if (gid < NXQ)            { src = x;    dst = g_xh;            q = gid; }
        else if (gid < NXQ + NWQ) { src = Wih0; dst = g_Wh;            q = gid - NXQ; }
        else                      { src = Wih1; dst = g_Wh + G4 * K_;  q = gid - NXQ - NWQ; }
        float4 v = *(const float4*)(src + (size_t)q * 4);
        *(__half2*)(dst + (size_t)q * 4)     = __floats2half2_rn(v.x, v.y);
        *(__half2*)(dst + (size_t)q * 4 + 2) = __floats2half2_rn(v.z, v.w);
    }
    if (gid < B_ * H_ / 4) {
        __half z = __float2half(0.f);
        __half2 z2 = __halves2half2(z, z);
        *(__half2*)(g_hA + gid * 4)     = z2;
        *(__half2*)(g_hA + gid * 4 + 2) = z2;
        *(__half2*)(g_hB + gid * 4)     = z2;
        *(__half2*)(g_hB + gid * 4 + 2) = z2;
    }
    if (gid == 0) g_bar = 0u;
}

// ---------------- input projection GEMM: 3-stage pipeline (R11/R13 winner) ----------------
#define BM 128
#define BN 128
#define BKH 32
#define GSTR 40
#define ASZ (BM * GSTR * 2)              // bytes per stage (10240)
#define GSMEM (3 * 2 * ASZ)              // 61440 bytes

__global__ __launch_bounds__(256, 2)
void gemm_ih_kernel(int asel, int woff, const float* __restrict__ bias) {
    const __half* A = asel ? g_y1h : g_xh;
    const __half* W = g_Wh + (size_t)woff * (G4 * K_);

    extern __shared__ __half gsm[];
    uint32_t sa = (uint32_t)__cvta_generic_to_shared(gsm);            // 3 A stages
    uint32_t sb = sa + 3 * ASZ;                                        // 3 B stages

    int tid  = threadIdx.x;
    int bm   = blockIdx.y * BM;
    int bn   = blockIdx.x * BN;
    int warp = tid >> 5, lane = tid & 31;
    int gid  = lane >> 2, tig = lane & 3;
    int wm   = (warp & 3) * 32;
    int wn   = (warp >> 2) * 64;

    int r0   = tid >> 2;
    int gcol = (tid & 3) * 8;
    const __half* Ap = A + (size_t)(bm + r0) * K_ + gcol;
    const __half* Wp = W + (size_t)(bn + r0) * K_ + gcol;
    uint32_t da0 = sa + (uint32_t)(r0 * GSTR + gcol) * 2;
    uint32_t da1 = sa + (uint32_t)((r0 + 64) * GSTR + gcol) * 2;
    uint32_t db0 = sb + (uint32_t)(r0 * GSTR + gcol) * 2;
    uint32_t db1 = sb + (uint32_t)((r0 + 64) * GSTR + gcol) * 2;

    uint32_t a_off = (uint32_t)(((lane & 7) + ((lane >> 3) & 1) * 8) * GSTR + (lane >> 4) * 8) * 2;
    uint32_t b_off = (uint32_t)(((lane & 7) + ((lane >> 4) & 1) * 8) * GSTR + ((lane >> 3) & 1) * 8) * 2;

    float c[2][8][4];
#pragma unroll
    for (int i = 0; i < 2; i++)
#pragma unroll
        for (int j = 0; j < 8; j++)
#pragma unroll
            for (int q = 0; q < 4; q++) c[i][j][q] = 0.f;

#define G_LOAD(it, stg_)                                                      \
    do {                                                                      \
        int k_ = (it) * BKH;                                                  \
        uint32_t so_ = (uint32_t)(stg_) * ASZ;                                \
        CP_ASYNC_CG(da0 + so_, Ap + k_);                                      \
        CP_ASYNC_CG(da1 + so_, Ap + (size_t)64 * K_ + k_);                    \
        CP_ASYNC_CG(db0 + so_, Wp + k_);                                      \
        CP_ASYNC_CG(db1 + so_, Wp + (size_t)64 * K_ + k_);                    \
        CP_COMMIT();                                                          \
    } while (0)

    const int NIT = K_ / BKH;   // 32
    G_LOAD(0, 0);               // group g0 -> stage 0
    G_LOAD(1, 1);               // group g1 -> stage 1

    int stg = 0;
    for (int it = 0; it < NIT; it++) {
        // pending before wait: {g_it, g_{it+1}} (2) except last iter: {g_it} (1)
        if (it == NIT - 1) CP_WAIT(0);
        else               CP_WAIT(1);
        __syncthreads();   // g_it visible AND all reads of stage (stg+2)%3 done

        if (it + 2 < NIT) {
            int nst = stg + 2; if (nst >= 3) nst -= 3;
            G_LOAD(it + 2, nst);
        }

        uint32_t sAs = sa + (uint32_t)stg * ASZ;
        uint32_t sBs = sb + (uint32_t)stg * ASZ;
#pragma unroll
        for (int ks = 0; ks < 2; ks++) {
            uint32_t af[2][4], bf[8][2];
#pragma unroll
            for (int mi = 0; mi < 2; mi++)
                ldsm_x4(af[mi][0], af[mi][1], af[mi][2], af[mi][3],
                        sAs + (uint32_t)((wm + mi * 16) * GSTR) * 2 + a_off + ks * 32);
#pragma unroll
            for (int nj = 0; nj < 4; nj++)
                ldsm_x4(bf[2 * nj][0], bf[2 * nj][1], bf[2 * nj + 1][0], bf[2 * nj + 1][1],
                        sBs + (uint32_t)((wn + nj * 16) * GSTR) * 2 + b_off + ks * 32);
#pragma unroll
            for (int mi = 0; mi < 2; mi++)
#pragma unroll
                for (int nj = 0; nj < 8; nj++)
                    mma_f16(c[mi][nj], af[mi], bf[nj]);
        }
        if (++stg >= 3) stg = 0;
    }
#undef G_LOAD

#pragma unroll
    for (int mi = 0; mi < 2; mi++) {
#pragma unroll
        for (int nj = 0; nj < 8; nj++) {
            int m0 = bm + wm + mi * 16 + gid;
            int n0 = bn + wn + nj * 8 + 2 * tig;
            float b0v = bias[n0], b1v = bias[n0 + 1];
            size_t o = (size_t)m0 * G4 + n0;
            g_ih[o]                      = c[mi][nj][0] + b0v;
            g_ih[o + 1]                  = c[mi][nj][1] + b1v;
            g_ih[o + (size_t)8 * G4]     = c[mi][nj][2] + b0v;
            g_ih[o + (size_t)8 * G4 + 1] = c[mi][nj][3] + b1v;
        }
    }
}

// ---------------- persistent recurrence kernel (R13 winner + self-clean) ----------------
// bar_base: barrier counter continues across the two layer launches (no reset).
// After the final step's barrier (all CTAs' reads provably done), each CTA
// zeroes its own 8 h-columns in both buffers for the next layer.
#define WSTR 1032
#define HSTR 1032
#define PERSIST_SMEM ((32*WSTR + 32*HSTR) * 2 + 2 * 32 * 33 * 4)

__global__ __launch_bounds__(256, 1)
void lstm_persist_kernel(const float* __restrict__ Whh_raw, int outsel,
                         float* __restrict__ out_ext, unsigned bar_base)
{
    extern __shared__ __half smh[];
    __half* Wsm = smh;
    __half* Hsm = Wsm + 32 * WSTR;
    float*  Ps  = (float*)(Hsm + 32 * HSTR);

    int tid  = threadIdx.x;
    int warp = tid >> 5, lane = tid & 31;
    int gid  = lane >> 2, tig = lane & 3;
    int kh   = warp & 1;
    int nj   = (warp >> 1) & 1;
    int mi   = warp >> 2;
    int j0   = blockIdx.x * 8;

#pragma unroll 4
    for (int i = 0; i < 32; i++) {
        int idx = i * 256 + tid;
        int r   = idx >> 8;
        int c4  = idx & 255;
        int g   = r >> 3, jr = r & 7;
        const float4 v = *(const float4*)(Whh_raw + ((size_t)(g * H_ + j0 + jr)) * K_ + c4 * 4);
        *(__half2*)&Wsm[r * WSTR + c4 * 4]     = __floats2half2_rn(v.x, v.y);
        *(__half2*)&Wsm[r * WSTR + c4 * 4 + 2] = __floats2half2_rn(v.z, v.w);
    }

    uint32_t hs_base = (uint32_t)__cvta_generic_to_shared(Hsm);
    uint32_t ws_base = (uint32_t)__cvta_generic_to_shared(Wsm);
    uint32_t a_base = hs_base +
        (uint32_t)((mi * 16 + (lane & 7) + ((lane >> 3) & 1) * 8) * HSTR +
                   (lane >> 4) * 8 + kh * 512) * 2;
    uint32_t b_base = ws_base +
        (uint32_t)((nj * 16 + (lane & 7) + ((lane >> 4) & 1) * 8) * WSTR +
                   ((lane >> 3) & 1) * 8 + kh * 512) * 2;

    int hrow = tid >> 5;
    int hcol = lane * 8;
    int b    = tid >> 3;
    int jj   = tid & 7;
    float c_state = 0.f;
    float* Pk = Ps + kh * (32 * 33);

    __syncthreads();

    size_t ihbase = ((size_t)b * T_) * G4 + j0 + jj;
    float ih0 = __ldcs(&g_ih[ihbase]);
    float ih1 = __ldcs(&g_ih[ihbase + H_]);
    float ih2 = __ldcs(&g_ih[ihbase + 2 * H_]);
    float ih3 = __ldcs(&g_ih[ihbase + 3 * H_]);

    for (int t = 0; t < T_; t++) {
        const __half* hin  = (t & 1) ? g_hB : g_hA;
        __half*       hout = (t & 1) ? g_hA : g_hB;

        uint4 rv[16];
#pragma unroll
        for (int p = 0; p < 4; p++)
#pragma unroll
            for (int q = 0; q < 4; q++)
                rv[p * 4 + q] = __ldcg((const uint4*)(hin + (size_t)(hrow + 8 * p) * H_ +
                                                       q * 256 + hcol));
#pragma unroll
        for (int p = 0; p < 4; p++)
#pragma unroll
            for (int q = 0; q < 4; q++)
                *(uint4*)&Hsm[(hrow + 8 * p) * HSTR + q * 256 + hcol] = rv[p * 4 + q];
        __syncthreads();

        float acc0[4] = {0.f, 0.f, 0.f, 0.f};
        float acc1[4] = {0.f, 0.f, 0.f, 0.f};
        uint32_t aaddr = a_base, baddr = b_base;
#pragma unroll
        for (int ks = 0; ks < 32; ks++) {
            uint32_t af[4], bl[2], bhh[2];
            ldsm_x4(af[0], af[1], af[2], af[3], aaddr);
            ldsm_x4(bl[0], bl[1], bhh[0], bhh[1], baddr);
            mma_f16(acc0, af, bl);
            mma_f16(acc1, af, bhh);
            aaddr += 32;
            baddr += 32;
        }

        {
            int m = mi * 16 + gid;
            int n = nj * 16 + 2 * tig;
            Pk[m * 33 + n]               = acc0[0];
            Pk[m * 33 + n + 1]           = acc0[1];
            Pk[(m + 8) * 33 + n]         = acc0[2];
            Pk[(m + 8) * 33 + n + 1]     = acc0[3];
            Pk[m * 33 + n + 8]           = acc1[0];
            Pk[m * 33 + n + 9]           = acc1[1];
            Pk[(m + 8) * 33 + n + 8]     = acc1[2];
            Pk[(m + 8) * 33 + n + 9]     = acc1[3];
        }
        __syncthreads();

        float hv;
        __half hr;
        {
            const float* P0 = Ps;
            const float* P1 = Ps + 32 * 33;
            float ipre = P0[b * 33 + jj]      + P1[b * 33 + jj]      + ih0;
            float fpre = P0[b * 33 + 8 + jj]  + P1[b * 33 + 8 + jj]  + ih1;
            float gpre = P0[b * 33 + 16 + jj] + P1[b * 33 + 16 + jj] + ih2;
            float opre = P0[b * 33 + 24 + jj] + P1[b * 33 + 24 + jj] + ih3;
            float iv = sig_f(ipre);
            float fv = sig_f(fpre);
            float gv = tanh_f(gpre);
            float ov = sig_f(opre);
            c_state = fv * c_state + iv * gv;
            hv = ov * tanh_f(c_state);
            hr = __float2half_rn(hv);
            unsigned short hb16 = __half_as_ushort(hr);
            asm volatile("st.global.cg.u16 [%0], %1;"
                         :: "l"(hout + b * H_ + j0 + jj), "h"(hb16) : "memory");
        }

        // ---- split grid barrier (R13: two-level release + direct counter poll) ----
        __syncthreads();                 // all hout stores ordered CTA-wide
        if (tid == 0) {
            asm volatile("red.release.gpu.global.add.u32 [%0], %1;"
                         :: "l"(&g_bar), "r"(1u) : "memory");
        }

        // hidden under the wait window: out store + next-step ih prefetch
        {
            size_t oidx = ((size_t)(b * T_ + t)) * H_ + j0 + jj;
            if (outsel) out_ext[oidx] = hv;
            else        g_y1h[oidx]   = hr;
            if (t + 1 < T_) {
                size_t ihn = ((size_t)(b * T_ + t + 1)) * G4 + j0 + jj;
                ih0 = __ldcs(&g_ih[ihn]);
                ih1 = __ldcs(&g_ih[ihn + H_]);
                ih2 = __ldcs(&g_ih[ihn + 2 * H_]);
                ih3 = __ldcs(&g_ih[ihn + 3 * H_]);
            }
        }

        // warp-distributed spin: lane 0 of each warp polls, then syncwarp
        {
            unsigned target = bar_base + (unsigned)NCTA * (unsigned)(t + 1);
            if (lane == 0) {
                unsigned v;
                do {
                    asm volatile("ld.acquire.gpu.global.u32 %0, [%1];"
                                 : "=r"(v) : "l"(&g_bar));
                } while (v < target);
            }
            __syncwarp();
        }
    }

    // ---- self-clean: final barrier proved all CTAs finished reading h ----
    {
        __half z = __float2half(0.f);
        g_hA[b * H_ + j0 + jj] = z;
        g_hB[b * H_ + j0 + jj] = z;
    }
}

// ---------------- launch ----------------
extern "C" void kernel_launch(void* const* d_in, const int* in_sizes, int n_in,
                              void* d_out, int out_size) {
    const float* x    = (const float*)d_in[0];
    const float* Wih0 = (const float*)d_in[1];
    const float* Whh0 = (const float*)d_in[2];
    const float* b0   = (const float*)d_in[3];
    const float* Wih1 = (const float*)d_in[4];
    const float* Whh1 = (const float*)d_in[5];
    const float* b1   = (const float*)d_in[6];
    float* out = (float*)d_out;

    static int attr_set = 0;
    if (!attr_set) {
        cudaFuncSetAttribute(lstm_persist_kernel,
                             cudaFuncAttributeMaxDynamicSharedMemorySize, PERSIST_SMEM);
        cudaFuncSetAttribute(gemm_ih_kernel,
                             cudaFuncAttributeMaxDynamicSharedMemorySize, GSMEM);
        attr_set = 1;
    }

    prep_kernel<<<(PREPQ + 255) / 256, 256>>>(x, Wih0, Wih1);

    dim3 ggrid(G4 / BN, M_ / BM);   // (32, 64)

    // layer 0 (barrier counts [0, NCTA*T])
    gemm_ih_kernel<<<ggrid, 256, GSMEM>>>(0, 0, b0);
    lstm_persist_kernel<<<NCTA, 256, PERSIST_SMEM>>>(Whh0, 0, nullptr, 0u);

    // layer 1 (barrier continues at NCTA*T; h buffers self-cleaned by layer 0)
    gemm_ih_kernel<<<ggrid, 256, GSMEM>>>(1, 1, b1);
    lstm_persist_kernel<<<NCTA, 256, PERSIST_SMEM>>>(Whh1, 1, out,
                                                     (unsigned)NCTA * (unsigned)T_);
}